// round 1
// baseline (speedup 1.0000x reference)
#include <cuda_runtime.h>
#include <math.h>

#define N_SEQ   2048
#define SEQ_LEN 24
#define SEQ_C   9
#define N_FILT  32
#define KM      16
#define HID     128
#define NCLS    10

// Scratch (allocation-free: __device__ globals)
__device__ float g_kT[KM * SEQ_C * N_FILT];   // kernels transposed: [i][c][f]
__device__ float g_knorm[KM * N_FILT];        // |kernel row|^2:    [i][f]
__device__ float g_feats[N_SEQ * N_FILT];     // DTW features

// ---------------------------------------------------------------------------
// Kernel 1: transpose kernels to [i][c][f] (coalesced lane-per-filter loads)
// and precompute per-row squared norms.
// ---------------------------------------------------------------------------
__global__ void prep_kernel(const float* __restrict__ kernels) {
    int idx = blockIdx.x * blockDim.x + threadIdx.x;
    if (idx >= KM * N_FILT) return;
    int i = idx >> 5;
    int f = idx & 31;
    float nrm = 0.f;
#pragma unroll
    for (int c = 0; c < SEQ_C; ++c) {
        float v = kernels[f * (KM * SEQ_C) + i * SEQ_C + c];
        g_kT[(i * SEQ_C + c) * N_FILT + f] = v;
        nrm = fmaf(v, v, nrm);
    }
    g_knorm[i * N_FILT + f] = nrm;
}

// ---------------------------------------------------------------------------
// Kernel 2: DTW forward DP. One warp per sequence, lane = filter.
// D[15][23] == backtracked path cost sum (exact-arithmetic identity).
// Rolling previous-row in registers; 5 kernel rows per sweep (3 sweeps for
// rows 1..15 after the row-0 cumsum).
// Local cost via C = knorm + snorm - 2*dot.
// ---------------------------------------------------------------------------
__global__ __launch_bounds__(32) void dtw_kernel(const float* __restrict__ x) {
    __shared__ float seqS[SEQ_LEN * SEQ_C];
    __shared__ float snormS[SEQ_LEN];

    const int s = blockIdx.x;
    const int f = threadIdx.x;

    // Stage this sequence (216 contiguous floats) into shared
    const float* xs = x + s * (SEQ_LEN * SEQ_C);
    for (int t = f; t < SEQ_LEN * SEQ_C; t += 32) seqS[t] = xs[t];
    __syncthreads();

    if (f < SEQ_LEN) {
        float a = 0.f;
#pragma unroll
        for (int c = 0; c < SEQ_C; ++c) {
            float v = seqS[f * SEQ_C + c];
            a = fmaf(v, v, a);
        }
        snormS[f] = a;
    }
    __syncthreads();

    float Dp[SEQ_LEN];  // previous DP row, fully register-resident

    // Row 0: cumulative sum of C[0][j]
    {
        float k0[SEQ_C];
#pragma unroll
        for (int c = 0; c < SEQ_C; ++c) k0[c] = g_kT[c * N_FILT + f];
        float kn = g_knorm[f];
        float run = 0.f;
#pragma unroll
        for (int j = 0; j < SEQ_LEN; ++j) {
            float dot = 0.f;
#pragma unroll
            for (int c = 0; c < SEQ_C; ++c) dot = fmaf(k0[c], seqS[j * SEQ_C + c], dot);
            float Cv = fmaf(-2.f, dot, kn + snormS[j]);
            run = (j == 0) ? Cv : (run + Cv);
            Dp[j] = run;
        }
    }

    const float INF = __int_as_float(0x7f800000);

    // Rows 1..15 in 3 sweeps of 5 rows each
    for (int sw = 0; sw < 3; ++sw) {
        const int i0 = 1 + sw * 5;
        float kr[5][SEQ_C], knr[5], left[5];
#pragma unroll
        for (int r = 0; r < 5; ++r) {
#pragma unroll
            for (int c = 0; c < SEQ_C; ++c)
                kr[r][c] = g_kT[((i0 + r) * SEQ_C + c) * N_FILT + f];
            knr[r] = g_knorm[(i0 + r) * N_FILT + f];
            left[r] = INF;
        }
        float diagc = INF;  // D[i0-1][j-1]
#pragma unroll
        for (int j = 0; j < SEQ_LEN; ++j) {
            float sv[SEQ_C];
#pragma unroll
            for (int c = 0; c < SEQ_C; ++c) sv[c] = seqS[j * SEQ_C + c];
            float sn = snormS[j];
            float up = Dp[j];       // D[i0-1][j]
            float oldup = up;
            float diag = diagc;     // D[i0-1][j-1]
#pragma unroll
            for (int r = 0; r < 5; ++r) {
                float dot = 0.f;
#pragma unroll
                for (int c = 0; c < SEQ_C; ++c) dot = fmaf(kr[r][c], sv[c], dot);
                float Cv = fmaf(-2.f, dot, knr[r] + sn);
                float best = fminf(left[r], fminf(up, diag));
                float d = Cv + best;
                diag = left[r];     // becomes D[i0+r][j-1] for next row
                left[r] = d;
                up = d;
            }
            Dp[j] = up;             // last sweep-row value at column j
            diagc = oldup;
        }
    }

    g_feats[s * N_FILT + f] = Dp[SEQ_LEN - 1];
}

// ---------------------------------------------------------------------------
// Kernel 3: MLP head. Block = 128 threads (one per hidden unit), 4 sequences
// per block. Weight loads coalesced, activations staged through shared.
// Logits + softmax per warp (warp w = sequence w of this block).
// ---------------------------------------------------------------------------
__global__ __launch_bounds__(128) void mlp_kernel(
    const float* __restrict__ W1, const float* __restrict__ b1,
    const float* __restrict__ W2, const float* __restrict__ b2,
    const float* __restrict__ Wl, const float* __restrict__ bl,
    float* __restrict__ out) {
    __shared__ float fS[4][N_FILT];
    __shared__ float t1S[4][HID];
    __shared__ float t2S[4][HID];

    const int t = threadIdx.x;
    const int s0 = blockIdx.x * 4;

    fS[t >> 5][t & 31] = g_feats[s0 * N_FILT + t];
    __syncthreads();

    // layer 1: 32 -> 128
    float a0 = b1[t], a1 = a0, a2 = a0, a3 = a0;
#pragma unroll
    for (int ff = 0; ff < N_FILT; ++ff) {
        float w = W1[ff * HID + t];
        a0 = fmaf(fS[0][ff], w, a0);
        a1 = fmaf(fS[1][ff], w, a1);
        a2 = fmaf(fS[2][ff], w, a2);
        a3 = fmaf(fS[3][ff], w, a3);
    }
    t1S[0][t] = fmaxf(a0, 0.f);
    t1S[1][t] = fmaxf(a1, 0.f);
    t1S[2][t] = fmaxf(a2, 0.f);
    t1S[3][t] = fmaxf(a3, 0.f);
    __syncthreads();

    // layer 2: 128 -> 128
    float c0 = b2[t], c1 = c0, c2 = c0, c3 = c0;
#pragma unroll 8
    for (int h = 0; h < HID; ++h) {
        float w = W2[h * HID + t];
        c0 = fmaf(t1S[0][h], w, c0);
        c1 = fmaf(t1S[1][h], w, c1);
        c2 = fmaf(t1S[2][h], w, c2);
        c3 = fmaf(t1S[3][h], w, c3);
    }
    t2S[0][t] = fmaxf(c0, 0.f);
    t2S[1][t] = fmaxf(c1, 0.f);
    t2S[2][t] = fmaxf(c2, 0.f);
    t2S[3][t] = fmaxf(c3, 0.f);
    __syncthreads();

    // logits (128 -> 10) + softmax: warp w handles sequence s0 + w
    const int wid = t >> 5;
    const int lane = t & 31;
    float acc[NCLS];
#pragma unroll
    for (int c = 0; c < NCLS; ++c) acc[c] = 0.f;
#pragma unroll
    for (int hh = 0; hh < 4; ++hh) {
        int h = lane + hh * 32;
        float v = t2S[wid][h];
#pragma unroll
        for (int c = 0; c < NCLS; ++c) acc[c] = fmaf(v, Wl[h * NCLS + c], acc[c]);
    }
#pragma unroll
    for (int off = 16; off > 0; off >>= 1) {
#pragma unroll
        for (int c = 0; c < NCLS; ++c)
            acc[c] += __shfl_xor_sync(0xffffffffu, acc[c], off);
    }
    if (lane == 0) {
        float mx = -__int_as_float(0x7f800000);
#pragma unroll
        for (int c = 0; c < NCLS; ++c) {
            acc[c] += bl[c];
            mx = fmaxf(mx, acc[c]);
        }
        float e[NCLS];
        float sum = 0.f;
#pragma unroll
        for (int c = 0; c < NCLS; ++c) {
            e[c] = expf(acc[c] - mx);
            sum += e[c];
        }
        float inv = 1.f / sum;
#pragma unroll
        for (int c = 0; c < NCLS; ++c)
            out[(s0 + wid) * NCLS + c] = e[c] * inv;
    }
}

// ---------------------------------------------------------------------------
extern "C" void kernel_launch(void* const* d_in, const int* in_sizes, int n_in,
                              void* d_out, int out_size) {
    const float* x       = (const float*)d_in[0];
    const float* kernels = (const float*)d_in[1];
    const float* W1      = (const float*)d_in[2];
    const float* b1      = (const float*)d_in[3];
    const float* W2      = (const float*)d_in[4];
    const float* b2      = (const float*)d_in[5];
    const float* Wl      = (const float*)d_in[6];
    const float* bl      = (const float*)d_in[7];
    float* out = (float*)d_out;

    prep_kernel<<<1, 512>>>(kernels);
    dtw_kernel<<<N_SEQ, 32>>>(x);
    mlp_kernel<<<N_SEQ / 4, 128>>>(W1, b1, W2, b2, Wl, bl, out);
}